// round 9
// baseline (speedup 1.0000x reference)
#include <cuda_runtime.h>
#include <stdint.h>

#define SHA_B 262144

__device__ __forceinline__ uint32_t rotr32(uint32_t x, int n) {
    return __funnelshift_r(x, x, n);
}

__global__ void __launch_bounds__(256) sha256_kernel(
    const uint32_t* __restrict__ msg,   // (B, 64) int32, byte values 0..255
    float* __restrict__ out)            // (B, 8) float32 digest words (signed-int32 semantics)
{
    const int tid = blockIdx.x * blockDim.x + threadIdx.x;
    if (tid >= SHA_B) return;

    constexpr uint32_t K[64] = {
        0x428a2f98u,0x71374491u,0xb5c0fbcfu,0xe9b5dba5u,0x3956c25bu,0x59f111f1u,0x923f82a4u,0xab1c5ed5u,
        0xd807aa98u,0x12835b01u,0x243185beu,0x550c7dc3u,0x72be5d74u,0x80deb1feu,0x9bdc06a7u,0xc19bf174u,
        0xe49b69c1u,0xefbe4786u,0x0fc19dc6u,0x240ca1ccu,0x2de92c6fu,0x4a7484aau,0x5cb0a9dcu,0x76f988dau,
        0x983e5152u,0xa831c66du,0xb00327c8u,0xbf597fc7u,0xc6e00bf3u,0xd5a79147u,0x06ca6351u,0x14292967u,
        0x27b70a85u,0x2e1b2138u,0x4d2c6dfcu,0x53380d13u,0x650a7354u,0x766a0abbu,0x81c2c92eu,0x92722c85u,
        0xa2bfe8a1u,0xa81a664bu,0xc24b8b70u,0xc76c51a3u,0xd192e819u,0xd6990624u,0xf40e3585u,0x106aa070u,
        0x19a4c116u,0x1e376c08u,0x2748774cu,0x34b0bcb5u,0x391c0cb3u,0x4ed8aa4au,0x5b9cca4fu,0x682e6ff3u,
        0x748f82eeu,0x78a5636fu,0x84c87814u,0x8cc70208u,0x90befffau,0xa4506cebu,0xbef9a3f7u,0xc67178f2u
    };

    // Each message = 64 consecutive int32 (one byte each), 256B per thread.
    const uint4* __restrict__ p = reinterpret_cast<const uint4*>(msg + (size_t)tid * 64);

    uint32_t W[16];
#pragma unroll
    for (int i = 0; i < 16; i++) {
        uint4 v = p[i];   // bytes 4i..4i+3
        W[i] = v.w + (v.z << 8) + (((v.x << 8) | v.y) << 16);
    }

    uint32_t a = 0x6a09e667u, b = 0xbb67ae85u, c = 0x3c6ef372u, d = 0xa54ff53au;
    uint32_t e = 0x510e527fu, f = 0x9b05688cu, g = 0x1f83d9abu, h = 0x5be0cd19u;

#pragma unroll
    for (int i = 0; i < 64; i++) {
        uint32_t wi;
        if (i < 16) {
            wi = W[i];
        } else {
            uint32_t x15 = W[(i + 1) & 15];
            uint32_t x2  = W[(i + 14) & 15];
            uint32_t s0 = rotr32(x15, 7) ^ rotr32(x15, 18) ^ (x15 >> 3);
            uint32_t s1 = rotr32(x2, 17) ^ rotr32(x2, 19) ^ (x2 >> 10);
            wi = W[i & 15] + s0 + W[(i + 9) & 15] + s1;
            W[i & 15] = wi;
        }
        uint32_t S1  = rotr32(e, 6) ^ rotr32(e, 11) ^ rotr32(e, 25);
        uint32_t ch  = (e & f) ^ (~e & g);              // one LOP3
        uint32_t t1  = h + S1 + ch + K[i] + wi;
        uint32_t S0  = rotr32(a, 2) ^ rotr32(a, 13) ^ rotr32(a, 22);
        uint32_t maj = (a & b) ^ (a & c) ^ (b & c);     // one LOP3
        uint32_t t2  = S0 + maj;
        h = g; g = f; f = e;
        e = d + t1;
        d = c; c = b; b = a;
        a = t1 + t2;
    }

    // Expected values are the digests wrapped through SIGNED int32 before the
    // float32 output cast (this is exactly the rel_err = sqrt(6) signature from R6).
    float4* o = reinterpret_cast<float4*>(out + (size_t)tid * 8);
    o[0] = make_float4((float)(int32_t)(a + 0x6a09e667u), (float)(int32_t)(b + 0xbb67ae85u),
                       (float)(int32_t)(c + 0x3c6ef372u), (float)(int32_t)(d + 0xa54ff53au));
    o[1] = make_float4((float)(int32_t)(e + 0x510e527fu), (float)(int32_t)(f + 0x9b05688cu),
                       (float)(int32_t)(g + 0x1f83d9abu), (float)(int32_t)(h + 0x5be0cd19u));
}

extern "C" void kernel_launch(void* const* d_in, const int* in_sizes, int n_in,
                              void* d_out, int out_size) {
    const uint32_t* msg = (const uint32_t*)d_in[0];
    float* out = (float*)d_out;
    const int threads = 256;
    const int blocks = (SHA_B + threads - 1) / threads;  // 1024
    sha256_kernel<<<blocks, threads>>>(msg, out);
}

// round 10
// speedup vs baseline: 1.6967x; 1.6967x over previous
#include <cuda_runtime.h>
#include <stdint.h>

#define SHA_B 262144
#define TPB 256

__device__ __forceinline__ uint32_t rotr32(uint32_t x, int n) {
    return __funnelshift_r(x, x, n);
}

__global__ void __launch_bounds__(TPB) sha256_kernel(
    const uint4* __restrict__ msg4,   // (B, 64) int32 viewed as uint4: 1 vec = 4 bytes = 1 SHA word
    float* __restrict__ out)          // (B, 8) float32 digest words (signed-int32 semantics)
{
    constexpr uint32_t K[64] = {
        0x428a2f98u,0x71374491u,0xb5c0fbcfu,0xe9b5dba5u,0x3956c25bu,0x59f111f1u,0x923f82a4u,0xab1c5ed5u,
        0xd807aa98u,0x12835b01u,0x243185beu,0x550c7dc3u,0x72be5d74u,0x80deb1feu,0x9bdc06a7u,0xc19bf174u,
        0xe49b69c1u,0xefbe4786u,0x0fc19dc6u,0x240ca1ccu,0x2de92c6fu,0x4a7484aau,0x5cb0a9dcu,0x76f988dau,
        0x983e5152u,0xa831c66du,0xb00327c8u,0xbf597fc7u,0xc6e00bf3u,0xd5a79147u,0x06ca6351u,0x14292967u,
        0x27b70a85u,0x2e1b2138u,0x4d2c6dfcu,0x53380d13u,0x650a7354u,0x766a0abbu,0x81c2c92eu,0x92722c85u,
        0xa2bfe8a1u,0xa81a664bu,0xc24b8b70u,0xc76c51a3u,0xd192e819u,0xd6990624u,0xf40e3585u,0x106aa070u,
        0x19a4c116u,0x1e376c08u,0x2748774cu,0x34b0bcb5u,0x391c0cb3u,0x4ed8aa4au,0x5b9cca4fu,0x682e6ff3u,
        0x748f82eeu,0x78a5636fu,0x84c87814u,0x8cc70208u,0x90befffau,0xa4506cebu,0xbef9a3f7u,0xc67178f2u
    };

    // Staging: 256 messages x 16 words, padded to 17 words/row for conflict-free LDS.
    __shared__ uint32_t sw[TPB * 17];

    const int t = threadIdx.x;
    const int block_msg0 = blockIdx.x * TPB;

    // ---- Load phase: fully coalesced. Block region = 256 msgs * 16 uint4 = 4096 vecs.
    // Linear vec index j -> message (j>>4), word (j&15). Pack big-endian in regs, STS.
    const uint4* __restrict__ src = msg4 + (size_t)block_msg0 * 16;
#pragma unroll
    for (int k = 0; k < 16; k++) {
        int j = t + k * TPB;
        uint4 v = src[j];   // 4 consecutive int32 bytes of one message word
        uint32_t w = v.w + (v.z << 8) + (((v.x << 8) | v.y) << 16);
        sw[(j >> 4) * 17 + (j & 15)] = w;
    }
    __syncthreads();

    // ---- Compute phase: thread t hashes message block_msg0 + t.
    uint32_t W[16];
#pragma unroll
    for (int i = 0; i < 16; i++) {
        W[i] = sw[t * 17 + i];   // lane bank stride 17 (coprime 32): conflict-free
    }

    uint32_t a = 0x6a09e667u, b = 0xbb67ae85u, c = 0x3c6ef372u, d = 0xa54ff53au;
    uint32_t e = 0x510e527fu, f = 0x9b05688cu, g = 0x1f83d9abu, h = 0x5be0cd19u;

#pragma unroll
    for (int i = 0; i < 64; i++) {
        uint32_t wi;
        if (i < 16) {
            wi = W[i];
        } else {
            uint32_t x15 = W[(i + 1) & 15];
            uint32_t x2  = W[(i + 14) & 15];
            uint32_t s0 = rotr32(x15, 7) ^ rotr32(x15, 18) ^ (x15 >> 3);
            uint32_t s1 = rotr32(x2, 17) ^ rotr32(x2, 19) ^ (x2 >> 10);
            wi = W[i & 15] + s0 + W[(i + 9) & 15] + s1;
            W[i & 15] = wi;
        }
        uint32_t S1  = rotr32(e, 6) ^ rotr32(e, 11) ^ rotr32(e, 25);
        uint32_t ch  = (e & f) ^ (~e & g);              // one LOP3
        uint32_t t1  = h + S1 + ch + K[i] + wi;
        uint32_t S0  = rotr32(a, 2) ^ rotr32(a, 13) ^ rotr32(a, 22);
        uint32_t maj = (a & b) ^ (a & c) ^ (b & c);     // one LOP3
        uint32_t t2  = S0 + maj;
        h = g; g = f; f = e;
        e = d + t1;
        d = c; c = b; b = a;
        a = t1 + t2;
    }

    // Signed wrap before float cast (matches harness's int64 -> float32 materialization).
    float4* o = reinterpret_cast<float4*>(out + (size_t)(block_msg0 + t) * 8);
    o[0] = make_float4((float)(int32_t)(a + 0x6a09e667u), (float)(int32_t)(b + 0xbb67ae85u),
                       (float)(int32_t)(c + 0x3c6ef372u), (float)(int32_t)(d + 0xa54ff53au));
    o[1] = make_float4((float)(int32_t)(e + 0x510e527fu), (float)(int32_t)(f + 0x9b05688cu),
                       (float)(int32_t)(g + 0x1f83d9abu), (float)(int32_t)(h + 0x5be0cd19u));
}

extern "C" void kernel_launch(void* const* d_in, const int* in_sizes, int n_in,
                              void* d_out, int out_size) {
    const uint4* msg4 = (const uint4*)d_in[0];
    float* out = (float*)d_out;
    const int blocks = SHA_B / TPB;  // 1024
    sha256_kernel<<<blocks, TPB>>>(msg4, out);
}

// round 13
// speedup vs baseline: 1.7404x; 1.0257x over previous
#include <cuda_runtime.h>
#include <stdint.h>

#define SHA_B 262144
#define TPB 256

__device__ __forceinline__ uint32_t rotr32(uint32_t x, int n) {
    return __funnelshift_r(x, x, n);
}

__global__ void __launch_bounds__(TPB, 6) sha256_kernel(
    const uint4* __restrict__ msg4,   // (B, 64) int32 viewed as uint4: 1 vec = 4 bytes = 1 SHA word
    float* __restrict__ out)          // (B, 8) float32 digest words (signed-int32 semantics)
{
    constexpr uint32_t K[64] = {
        0x428a2f98u,0x71374491u,0xb5c0fbcfu,0xe9b5dba5u,0x3956c25bu,0x59f111f1u,0x923f82a4u,0xab1c5ed5u,
        0xd807aa98u,0x12835b01u,0x243185beu,0x550c7dc3u,0x72be5d74u,0x80deb1feu,0x9bdc06a7u,0xc19bf174u,
        0xe49b69c1u,0xefbe4786u,0x0fc19dc6u,0x240ca1ccu,0x2de92c6fu,0x4a7484aau,0x5cb0a9dcu,0x76f988dau,
        0x983e5152u,0xa831c66du,0xb00327c8u,0xbf597fc7u,0xc6e00bf3u,0xd5a79147u,0x06ca6351u,0x14292967u,
        0x27b70a85u,0x2e1b2138u,0x4d2c6dfcu,0x53380d13u,0x650a7354u,0x766a0abbu,0x81c2c92eu,0x92722c85u,
        0xa2bfe8a1u,0xa81a664bu,0xc24b8b70u,0xc76c51a3u,0xd192e819u,0xd6990624u,0xf40e3585u,0x106aa070u,
        0x19a4c116u,0x1e376c08u,0x2748774cu,0x34b0bcb5u,0x391c0cb3u,0x4ed8aa4au,0x5b9cca4fu,0x682e6ff3u,
        0x748f82eeu,0x78a5636fu,0x84c87814u,0x8cc70208u,0x90befffau,0xa4506cebu,0xbef9a3f7u,0xc67178f2u
    };

    // Staging: 256 messages x 16 words, padded to 17 words/row for conflict-free LDS.
    __shared__ uint32_t sw[TPB * 17];

    const int t = threadIdx.x;
    const int block_msg0 = blockIdx.x * TPB;

    // ---- Load phase: fully coalesced. Block region = 256 msgs * 16 uint4 = 4096 vecs.
    // Pack via integer multiply-adds -> IMAD on the (mostly idle) fma pipe.
    const uint4* __restrict__ src = msg4 + (size_t)block_msg0 * 16;
#pragma unroll
    for (int k = 0; k < 16; k++) {
        int j = t + k * TPB;
        uint4 v = src[j];   // 4 consecutive int32 bytes of one message word
        uint32_t w = v.w + v.z * 256u + v.y * 65536u + v.x * 16777216u;
        sw[(j >> 4) * 17 + (j & 15)] = w;
    }
    __syncthreads();

    // ---- Compute phase: thread t hashes message block_msg0 + t. RAW W in the ring
    // (sigma functions are nonlinear: K must NOT be folded into stored words).
    uint32_t W[16];
#pragma unroll
    for (int i = 0; i < 16; i++) {
        W[i] = sw[t * 17 + i];   // stride 17 banks: conflict-free
    }

    uint32_t a = 0x6a09e667u, b = 0xbb67ae85u, c = 0x3c6ef372u, d = 0xa54ff53au;
    uint32_t e = 0x510e527fu, f = 0x9b05688cu, g = 0x1f83d9abu, h = 0x5be0cd19u;

#pragma unroll
    for (int i = 0; i < 64; i++) {
        // h, W[i], K[i] are all known >= 1 round early: these adds sit off the
        // e->S1->t1 critical path and can issue on the fma pipe as IMADs.
        uint32_t hk = h + (W[i & 15] + K[i]);
        if (i + 16 < 64) {
            // Schedule expansion on RAW words; result not needed for 16 rounds.
            uint32_t x15 = W[(i + 1) & 15];
            uint32_t x2  = W[(i + 14) & 15];
            uint32_t s0 = rotr32(x15, 7) ^ rotr32(x15, 18) ^ (x15 >> 3);
            uint32_t s1 = rotr32(x2, 17) ^ rotr32(x2, 19) ^ (x2 >> 10);
            W[i & 15] = W[i & 15] + s0 + W[(i + 9) & 15] + s1;
        }
        uint32_t S1  = rotr32(e, 6) ^ rotr32(e, 11) ^ rotr32(e, 25);
        uint32_t ch  = (e & f) ^ (~e & g);              // one LOP3
        uint32_t t1  = hk + S1 + ch;
        uint32_t S0  = rotr32(a, 2) ^ rotr32(a, 13) ^ rotr32(a, 22);
        uint32_t maj = (a & b) ^ (a & c) ^ (b & c);     // one LOP3
        uint32_t t2  = S0 + maj;
        h = g; g = f; f = e;
        e = d + t1;
        d = c; c = b; b = a;
        a = t1 + t2;
    }

    // Signed wrap before float cast (matches harness's int64 -> float32 materialization).
    float4* o = reinterpret_cast<float4*>(out + (size_t)(block_msg0 + t) * 8);
    o[0] = make_float4((float)(int32_t)(a + 0x6a09e667u), (float)(int32_t)(b + 0xbb67ae85u),
                       (float)(int32_t)(c + 0x3c6ef372u), (float)(int32_t)(d + 0xa54ff53au));
    o[1] = make_float4((float)(int32_t)(e + 0x510e527fu), (float)(int32_t)(f + 0x9b05688cu),
                       (float)(int32_t)(g + 0x1f83d9abu), (float)(int32_t)(h + 0x5be0cd19u));
}

extern "C" void kernel_launch(void* const* d_in, const int* in_sizes, int n_in,
                              void* d_out, int out_size) {
    const uint4* msg4 = (const uint4*)d_in[0];
    float* out = (float*)d_out;
    const int blocks = SHA_B / TPB;  // 1024
    sha256_kernel<<<blocks, TPB>>>(msg4, out);
}

// round 14
// speedup vs baseline: 1.7568x; 1.0094x over previous
#include <cuda_runtime.h>
#include <stdint.h>

#define SHA_B 262144
#define TPB 128
#define MPB 256   // messages per block (2 per thread)

__device__ __forceinline__ uint32_t rotr32(uint32_t x, int n) {
    return __funnelshift_r(x, x, n);
}

__global__ void __launch_bounds__(TPB, 7) sha256_kernel(
    const uint4* __restrict__ msg4,   // (B, 64) int32 viewed as uint4: 1 vec = 4 bytes = 1 SHA word
    float* __restrict__ out)          // (B, 8) float32 digest words (signed-int32 semantics)
{
    constexpr uint32_t K[64] = {
        0x428a2f98u,0x71374491u,0xb5c0fbcfu,0xe9b5dba5u,0x3956c25bu,0x59f111f1u,0x923f82a4u,0xab1c5ed5u,
        0xd807aa98u,0x12835b01u,0x243185beu,0x550c7dc3u,0x72be5d74u,0x80deb1feu,0x9bdc06a7u,0xc19bf174u,
        0xe49b69c1u,0xefbe4786u,0x0fc19dc6u,0x240ca1ccu,0x2de92c6fu,0x4a7484aau,0x5cb0a9dcu,0x76f988dau,
        0x983e5152u,0xa831c66du,0xb00327c8u,0xbf597fc7u,0xc6e00bf3u,0xd5a79147u,0x06ca6351u,0x14292967u,
        0x27b70a85u,0x2e1b2138u,0x4d2c6dfcu,0x53380d13u,0x650a7354u,0x766a0abbu,0x81c2c92eu,0x92722c85u,
        0xa2bfe8a1u,0xa81a664bu,0xc24b8b70u,0xc76c51a3u,0xd192e819u,0xd6990624u,0xf40e3585u,0x106aa070u,
        0x19a4c116u,0x1e376c08u,0x2748774cu,0x34b0bcb5u,0x391c0cb3u,0x4ed8aa4au,0x5b9cca4fu,0x682e6ff3u,
        0x748f82eeu,0x78a5636fu,0x84c87814u,0x8cc70208u,0x90befffau,0xa4506cebu,0xbef9a3f7u,0xc67178f2u
    };

    // Staging: 256 messages x 16 words, padded to 17 words/row for conflict-free LDS.
    __shared__ uint32_t sw[MPB * 17];

    const int t = threadIdx.x;
    const int block_msg0 = blockIdx.x * MPB;

    // ---- Load phase: fully coalesced. Block region = 256 msgs * 16 uint4 = 4096 vecs.
    const uint4* __restrict__ src = msg4 + (size_t)block_msg0 * 16;
#pragma unroll
    for (int k = 0; k < 32; k++) {
        int j = t + k * TPB;
        uint4 v = src[j];   // 4 consecutive int32 bytes of one message word
        uint32_t w = v.w + v.z * 256u + v.y * 65536u + v.x * 16777216u;
        sw[(j >> 4) * 17 + (j & 15)] = w;
    }
    __syncthreads();

    // ---- Compute phase: thread t hashes messages (block_msg0 + t) and (block_msg0 + t + 128).
    // Two fully independent states interleaved -> ILP 2 inside each warp.
    uint32_t W0[16], W1[16];
#pragma unroll
    for (int i = 0; i < 16; i++) {
        W0[i] = sw[t * 17 + i];
        W1[i] = sw[(t + TPB) * 17 + i];
    }

    uint32_t a0 = 0x6a09e667u, b0 = 0xbb67ae85u, c0 = 0x3c6ef372u, d0 = 0xa54ff53au;
    uint32_t e0 = 0x510e527fu, f0 = 0x9b05688cu, g0 = 0x1f83d9abu, h0 = 0x5be0cd19u;
    uint32_t a1 = 0x6a09e667u, b1 = 0xbb67ae85u, c1 = 0x3c6ef372u, d1 = 0xa54ff53au;
    uint32_t e1 = 0x510e527fu, f1 = 0x9b05688cu, g1 = 0x1f83d9abu, h1 = 0x5be0cd19u;

#pragma unroll
    for (int i = 0; i < 64; i++) {
        const uint32_t k = K[i];
        // --- state 0 ---
        {
            uint32_t hk = h0 + (W0[i & 15] + k);
            if (i + 16 < 64) {
                uint32_t x15 = W0[(i + 1) & 15];
                uint32_t x2  = W0[(i + 14) & 15];
                uint32_t s0 = rotr32(x15, 7) ^ rotr32(x15, 18) ^ (x15 >> 3);
                uint32_t s1 = rotr32(x2, 17) ^ rotr32(x2, 19) ^ (x2 >> 10);
                W0[i & 15] = W0[i & 15] + s0 + W0[(i + 9) & 15] + s1;
            }
            uint32_t S1  = rotr32(e0, 6) ^ rotr32(e0, 11) ^ rotr32(e0, 25);
            uint32_t ch  = (e0 & f0) ^ (~e0 & g0);
            uint32_t t1  = hk + S1 + ch;
            uint32_t S0  = rotr32(a0, 2) ^ rotr32(a0, 13) ^ rotr32(a0, 22);
            uint32_t maj = (a0 & b0) ^ (a0 & c0) ^ (b0 & c0);
            uint32_t t2  = S0 + maj;
            h0 = g0; g0 = f0; f0 = e0;
            e0 = d0 + t1;
            d0 = c0; c0 = b0; b0 = a0;
            a0 = t1 + t2;
        }
        // --- state 1 (independent: interleaves with state 0's latency) ---
        {
            uint32_t hk = h1 + (W1[i & 15] + k);
            if (i + 16 < 64) {
                uint32_t x15 = W1[(i + 1) & 15];
                uint32_t x2  = W1[(i + 14) & 15];
                uint32_t s0 = rotr32(x15, 7) ^ rotr32(x15, 18) ^ (x15 >> 3);
                uint32_t s1 = rotr32(x2, 17) ^ rotr32(x2, 19) ^ (x2 >> 10);
                W1[i & 15] = W1[i & 15] + s0 + W1[(i + 9) & 15] + s1;
            }
            uint32_t S1  = rotr32(e1, 6) ^ rotr32(e1, 11) ^ rotr32(e1, 25);
            uint32_t ch  = (e1 & f1) ^ (~e1 & g1);
            uint32_t t1  = hk + S1 + ch;
            uint32_t S0  = rotr32(a1, 2) ^ rotr32(a1, 13) ^ rotr32(a1, 22);
            uint32_t maj = (a1 & b1) ^ (a1 & c1) ^ (b1 & c1);
            uint32_t t2  = S0 + maj;
            h1 = g1; g1 = f1; f1 = e1;
            e1 = d1 + t1;
            d1 = c1; c1 = b1; b1 = a1;
            a1 = t1 + t2;
        }
    }

    // Signed wrap before float cast (matches harness's int64 -> float32 materialization).
    float4* o0 = reinterpret_cast<float4*>(out + (size_t)(block_msg0 + t) * 8);
    o0[0] = make_float4((float)(int32_t)(a0 + 0x6a09e667u), (float)(int32_t)(b0 + 0xbb67ae85u),
                        (float)(int32_t)(c0 + 0x3c6ef372u), (float)(int32_t)(d0 + 0xa54ff53au));
    o0[1] = make_float4((float)(int32_t)(e0 + 0x510e527fu), (float)(int32_t)(f0 + 0x9b05688cu),
                        (float)(int32_t)(g0 + 0x1f83d9abu), (float)(int32_t)(h0 + 0x5be0cd19u));
    float4* o1 = reinterpret_cast<float4*>(out + (size_t)(block_msg0 + t + TPB) * 8);
    o1[0] = make_float4((float)(int32_t)(a1 + 0x6a09e667u), (float)(int32_t)(b1 + 0xbb67ae85u),
                        (float)(int32_t)(c1 + 0x3c6ef372u), (float)(int32_t)(d1 + 0xa54ff53au));
    o1[1] = make_float4((float)(int32_t)(e1 + 0x510e527fu), (float)(int32_t)(f1 + 0x9b05688cu),
                        (float)(int32_t)(g1 + 0x1f83d9abu), (float)(int32_t)(h1 + 0x5be0cd19u));
}

extern "C" void kernel_launch(void* const* d_in, const int* in_sizes, int n_in,
                              void* d_out, int out_size) {
    const uint4* msg4 = (const uint4*)d_in[0];
    float* out = (float*)d_out;
    const int blocks = SHA_B / MPB;  // 1024
    sha256_kernel<<<blocks, TPB>>>(msg4, out);
}